// round 15
// baseline (speedup 1.0000x reference)
#include <cuda_runtime.h>
#include <cstdint>

// CrossAttention collapses: K/V are one visual_features vector broadcast over
// all T keys; softmax over identical logits is uniform, so y == v everywhere:
//   out[b,t,:] = ((vf[b] @ Wv + bv) @ Wp + bp)   broadcast over t.
// x / Wq / bq / Wk / bk are mathematically dead.
//
// R10 finding: STG, TMA, and LDG+STG broadcasts all hit ~6.8us => external
// store floor; bcast internals are done. Remaining cost is synchronization:
// graph-node gaps ~1.9us each (R4) vs software barriers ~2.5us each (R5).
// R14: R5's persistent single-kernel design with a CHEAP grid barrier —
// relaxed polls + nanosleep backoff instead of hot ld.acquire spinning.

#define CDIM  1024
#define BDIM  4
#define TDIM  1024
#define GBLK  256             // grid blocks (4 batches x 64 k-chunks)
#define NTHR  256
#define KS    64              // split-K chunk count
#define ROWS  (CDIM / KS)     // 16 reduction rows per chunk
#define TT    (TDIM / KS)     // 16 t-rows per block in bcast phase

__device__ float g_pvv[KS][BDIM][CDIM];  // partials of vf @ Wv
__device__ float g_pr [KS][BDIM][CDIM];  // partials of vv @ Wp
__device__ float g_r  [BDIM][CDIM];      // final row to broadcast
__device__ unsigned g_barctr[4];         // monotonic barrier counters

// Monotonic-ticket grid barrier (replay-safe: counters never reset).
// Cheap wait: one relaxed probe, then nanosleep-backoff relaxed polls; a
// single ld.acquire closes the barrier with acquire semantics.
__device__ __forceinline__ void grid_barrier(int idx)
{
    __syncthreads();
    if (threadIdx.x == 0) {
        __threadfence();                                  // release our writes
        unsigned t = atomicAdd(&g_barctr[idx], 1u);
        unsigned target = (t / GBLK + 1u) * GBLK;         // end of this round
        unsigned v;
        asm volatile("ld.relaxed.gpu.global.u32 %0, [%1];"
                     : "=r"(v) : "l"(&g_barctr[idx]));
        while (v < target) {
            __nanosleep(64);
            asm volatile("ld.relaxed.gpu.global.u32 %0, [%1];"
                         : "=r"(v) : "l"(&g_barctr[idx]));
        }
        asm volatile("ld.acquire.gpu.global.u32 %0, [%1];"  // acquire close
                     : "=r"(v) : "l"(&g_barctr[idx]));
    }
    __syncthreads();
}

__global__ __launch_bounds__(NTHR) void fused_kernel(
    const float* __restrict__ vf,
    const float* __restrict__ Wv, const float* __restrict__ bv,
    const float* __restrict__ Wp, const float* __restrict__ bp,
    float4* __restrict__ out)
{
    __shared__ float s_in[ROWS];
    __shared__ float s_red[16][ROWS];

    const int tid = threadIdx.x;
    const int b   = blockIdx.x >> 6;   // 0..3
    const int k   = blockIdx.x & 63;   // 0..63
    const int j0  = tid * 4;           // this thread's 4 output columns

    // ---- Phase 1: g_pvv[k][b][:] = sum_{i in chunk k} vf[b,i] * Wv[i,:] ----
    if (tid < ROWS)
        s_in[tid] = vf[b * CDIM + k * ROWS + tid];
    __syncthreads();
    {
        float4 acc = make_float4(0.f, 0.f, 0.f, 0.f);
        #pragma unroll
        for (int i = 0; i < ROWS; ++i) {
            const float4 w = __ldg((const float4*)&Wv[(k * ROWS + i) * CDIM + j0]);
            const float s = s_in[i];
            acc.x += s * w.x; acc.y += s * w.y; acc.z += s * w.z; acc.w += s * w.w;
        }
        *(float4*)&g_pvv[k][b][j0] = acc;
    }

    grid_barrier(0);

    // ---- Phase 2: reduce needed vv slice (+bv), then partials of @ Wp ----
    {
        const int i  = tid & (ROWS - 1);   // 0..15
        const int kg = tid >> 4;           // 0..15, 4 partials each
        float s = 0.f;
        #pragma unroll
        for (int kk = kg * 4; kk < kg * 4 + 4; ++kk)
            s += g_pvv[kk][b][k * ROWS + i];
        s_red[kg][i] = s;
    }
    __syncthreads();
    if (tid < ROWS) {
        float s = bv[k * ROWS + tid];
        #pragma unroll
        for (int g = 0; g < 16; ++g)
            s += s_red[g][tid];
        s_in[tid] = s;
    }
    __syncthreads();
    {
        float4 acc = make_float4(0.f, 0.f, 0.f, 0.f);
        #pragma unroll
        for (int i = 0; i < ROWS; ++i) {
            const float4 w = __ldg((const float4*)&Wp[(k * ROWS + i) * CDIM + j0]);
            const float s = s_in[i];
            acc.x += s * w.x; acc.y += s * w.y; acc.z += s * w.z; acc.w += s * w.w;
        }
        *(float4*)&g_pr[k][b][j0] = acc;
    }

    grid_barrier(1);

    // ---- Phase 3: blocks 0..15 reduce 64 partials -> g_r (+bp) ----
    if (blockIdx.x < 16) {
        const int idx = blockIdx.x * NTHR + tid;   // 0..4095
        const int rb = idx >> 10;
        const int rj = idx & (CDIM - 1);
        float s = bp[rj];
        #pragma unroll
        for (int kk = 0; kk < KS; ++kk)
            s += g_pr[kk][rb][rj];
        g_r[rb][rj] = s;
    }

    grid_barrier(2);

    // ---- Phase 4: out[b, t0..t0+15, :] = g_r[b, :] ----
    {
        const int t0 = k * TT;
        const float4 v = *(const float4*)&g_r[b][j0];
        float4* __restrict__ p = out + (size_t)(b * TDIM + t0) * (CDIM / 4) + tid;
        #pragma unroll
        for (int t = 0; t < TT; ++t)
            p[t * (CDIM / 4)] = v;
    }
}

extern "C" void kernel_launch(void* const* d_in, const int* in_sizes, int n_in,
                              void* d_out, int out_size)
{
    (void)in_sizes; (void)n_in; (void)out_size;
    const float* vf = (const float*)d_in[1];
    const float* Wv = (const float*)d_in[6];
    const float* bv = (const float*)d_in[7];
    const float* Wp = (const float*)d_in[8];
    const float* bp = (const float*)d_in[9];

    fused_kernel<<<GBLK, NTHR>>>(vf, Wv, bv, Wp, bp, (float4*)d_out);
}